// round 1
// baseline (speedup 1.0000x reference)
#include <cuda_runtime.h>
#include <math.h>

// ---------------- problem constants ----------------
#define Tn    8192          // B*S tokens
#define Dn    1024          // d_model
#define NCOLSn 32
#define FSn   16
#define NEFn  8
#define En    8
#define DFEn  64
#define DRHn  256
#define DEHn  2048
#define KINn  (Dn + DFEn)   // 1088
#define EPSf  1e-5f

// ---------------- scratch (__device__ globals; no allocs allowed) ----------------
__device__ float g_hln [Tn * Dn];            // 32 MB  layernormed h
__device__ float g_femb[Tn * DFEn];          //  2 MB  router stage-feature embedding
__device__ float g_hr  [Tn * DRHn];          //  8 MB  router hidden
__device__ int   g_cnt [En];                 // tokens per expert
__device__ int   g_plist[En * Tn];           // slot list per expert (slot = token*2 + k)
__device__ int   g_toke[Tn * 2];             // expert id per slot
__device__ float g_tokw[Tn * 2];             // gate weight per slot
__device__ float g_eemb[Tn * 2 * DFEn];      //  4 MB  expert feature embedding per slot
__device__ float g_hh  [Tn * 2 * DEHn];      // 128 MB expert hidden per slot
__device__ float g_eo  [Tn * 2 * Dn];        // 64 MB  expert output per slot

__device__ __forceinline__ float gelu_f(float x) {
    // jax.nn.gelu default: tanh approximation
    float x3 = x * x * x;
    return 0.5f * x * (1.0f + tanhf(0.7978845608028654f * (x + 0.044715f * x3)));
}

// ---------------- K1: layernorm + stage-feature embedding ----------------
__global__ __launch_bounds__(256) void k_ln(
    const float* __restrict__ h, const float* __restrict__ feat,
    const float* __restrict__ ln_g, const float* __restrict__ ln_b,
    const float* __restrict__ Wsf, const float* __restrict__ bsf,
    const int* __restrict__ stage_idx)
{
    const int t = blockIdx.x;
    const int tid = threadIdx.x;
    const float4 xv = ((const float4*)(h + (size_t)t * Dn))[tid];

    float s  = xv.x + xv.y + xv.z + xv.w;
    float s2 = xv.x * xv.x + xv.y * xv.y + xv.z * xv.z + xv.w * xv.w;
    #pragma unroll
    for (int o = 16; o > 0; o >>= 1) {
        s  += __shfl_xor_sync(0xffffffffu, s,  o);
        s2 += __shfl_xor_sync(0xffffffffu, s2, o);
    }
    __shared__ float rs[8], rs2[8], stats[2];
    if ((tid & 31) == 0) { rs[tid >> 5] = s; rs2[tid >> 5] = s2; }
    __syncthreads();
    if (tid == 0) {
        float a = 0.f, a2 = 0.f;
        #pragma unroll
        for (int i = 0; i < 8; i++) { a += rs[i]; a2 += rs2[i]; }
        float m = a * (1.0f / Dn);
        stats[0] = m;
        stats[1] = rsqrtf(a2 * (1.0f / Dn) - m * m + EPSf);
    }
    __shared__ float sf[FSn];
    if (tid < FSn) sf[tid] = feat[(size_t)t * NCOLSn + stage_idx[tid]];
    __syncthreads();

    const float m = stats[0], r = stats[1];
    const float4 gv = ((const float4*)ln_g)[tid];
    const float4 bv = ((const float4*)ln_b)[tid];
    float4 o;
    o.x = (xv.x - m) * r * gv.x + bv.x;
    o.y = (xv.y - m) * r * gv.y + bv.y;
    o.z = (xv.z - m) * r * gv.z + bv.z;
    o.w = (xv.w - m) * r * gv.w + bv.w;
    ((float4*)(g_hln + (size_t)t * Dn))[tid] = o;

    if (tid < DFEn) {
        float acc = bsf[tid];
        #pragma unroll
        for (int f = 0; f < FSn; f++) acc = fmaf(sf[f], Wsf[f * DFEn + tid], acc);
        g_femb[(size_t)t * DFEn + tid] = acc;
    }
}

__global__ void k_zero() { if (threadIdx.x < En) g_cnt[threadIdx.x] = 0; }

// ---------------- K2: router GEMM1  hr = gelu([hln|femb] @ Wr1 + br1) ----------------
__global__ __launch_bounds__(256) void k_router_gemm(
    const float* __restrict__ W, const float* __restrict__ bias)
{
    __shared__ float As[16][64];
    __shared__ float Bs[16][64];
    const int m0 = blockIdx.y * 64, n0 = blockIdx.x * 64;
    const int tid = threadIdx.x;
    const int tx = tid & 15, ty = tid >> 4;
    const int arow = tid >> 2, ak = (tid & 3) << 2;
    const int bk = tid >> 4,  bn = (tid & 15) << 2;
    float acc[4][4] = {};

    for (int k0 = 0; k0 < KINn; k0 += 16) {
        float4 av;
        if (k0 < Dn) av = *(const float4*)(g_hln  + (size_t)(m0 + arow) * Dn   + k0 + ak);
        else         av = *(const float4*)(g_femb + (size_t)(m0 + arow) * DFEn + (k0 - Dn) + ak);
        As[ak + 0][arow] = av.x; As[ak + 1][arow] = av.y;
        As[ak + 2][arow] = av.z; As[ak + 3][arow] = av.w;
        *(float4*)&Bs[bk][bn] = *(const float4*)(W + (size_t)(k0 + bk) * DRHn + n0 + bn);
        __syncthreads();
        #pragma unroll
        for (int kk = 0; kk < 16; kk++) {
            float4 a = *(const float4*)&As[kk][ty << 2];
            float4 b = *(const float4*)&Bs[kk][tx << 2];
            float ar[4] = {a.x, a.y, a.z, a.w}, br[4] = {b.x, b.y, b.z, b.w};
            #pragma unroll
            for (int i = 0; i < 4; i++)
                #pragma unroll
                for (int j = 0; j < 4; j++) acc[i][j] = fmaf(ar[i], br[j], acc[i][j]);
        }
        __syncthreads();
    }
    float4 bv = *(const float4*)(bias + n0 + (tx << 2));
    float bb[4] = {bv.x, bv.y, bv.z, bv.w};
    #pragma unroll
    for (int i = 0; i < 4; i++) {
        int m = m0 + (ty << 2) + i;
        float4 o;
        o.x = gelu_f(acc[i][0] + bb[0]);
        o.y = gelu_f(acc[i][1] + bb[1]);
        o.z = gelu_f(acc[i][2] + bb[2]);
        o.w = gelu_f(acc[i][3] + bb[3]);
        *(float4*)(g_hr + (size_t)m * DRHn + n0 + (tx << 2)) = o;
    }
}

// ---------------- K3: logits, top-2 softmax, per-expert scatter ----------------
__global__ __launch_bounds__(256) void k_router_topk(
    const float* __restrict__ Wr2, const float* __restrict__ br2)
{
    __shared__ float w2s[DRHn * En];
    for (int i = threadIdx.x; i < DRHn * En; i += blockDim.x) w2s[i] = Wr2[i];
    __syncthreads();

    const int t = blockIdx.x * blockDim.x + threadIdx.x;
    const float* hr = g_hr + (size_t)t * DRHn;
    float lg[En];
    #pragma unroll
    for (int e = 0; e < En; e++) lg[e] = br2[e];
    for (int k = 0; k < DRHn; k++) {
        float hv = hr[k];
        #pragma unroll
        for (int e = 0; e < En; e++) lg[e] = fmaf(hv, w2s[k * En + e], lg[e]);
    }
    // top-2 (ties -> lower index, matching lax.top_k)
    int e1 = 0; float v1 = lg[0];
    #pragma unroll
    for (int e = 1; e < En; e++) if (lg[e] > v1) { v1 = lg[e]; e1 = e; }
    int e2 = -1; float v2 = -1e30f;
    #pragma unroll
    for (int e = 0; e < En; e++) if (e != e1 && lg[e] > v2) { v2 = lg[e]; e2 = e; }
    float z = __expf(v2 - v1);   // softmax over [v1, v2], max-subtracted
    z = expf(v2 - v1);
    float w1 = 1.0f / (1.0f + z);
    float w2 = z / (1.0f + z);

    g_toke[t * 2 + 0] = e1; g_toke[t * 2 + 1] = e2;
    g_tokw[t * 2 + 0] = w1; g_tokw[t * 2 + 1] = w2;
    int p1 = atomicAdd(&g_cnt[e1], 1); g_plist[e1 * Tn + p1] = t * 2;
    int p2 = atomicAdd(&g_cnt[e2], 1); g_plist[e2 * Tn + p2] = t * 2 + 1;
}

// ---------------- K3b: expert feature embedding per slot ----------------
__global__ __launch_bounds__(64) void k_eemb(
    const float* __restrict__ feat, const float* __restrict__ Wef,
    const float* __restrict__ bef, const int* __restrict__ expert_idx)
{
    const int slot = blockIdx.x;
    const int e = g_toke[slot];
    const int t = slot >> 1;
    __shared__ float fv[NEFn];
    if (threadIdx.x < NEFn) {
        int col = expert_idx[e * NEFn + threadIdx.x];
        fv[threadIdx.x] = feat[(size_t)t * NCOLSn + col];
    }
    __syncthreads();
    const int d = threadIdx.x;
    float acc = bef[e * DFEn + d];
    #pragma unroll
    for (int f = 0; f < NEFn; f++)
        acc = fmaf(fv[f], Wef[((size_t)e * NEFn + f) * DFEn + d], acc);
    g_eemb[(size_t)slot * DFEn + d] = acc;
}

// ---------------- K4: expert GEMM1  hh = gelu([hln|eemb] @ We1[e] + be1[e]) ----------------
__global__ __launch_bounds__(256) void k_exp_gemm1(
    const float* __restrict__ We1, const float* __restrict__ be1)
{
    const int e = blockIdx.z;
    const int cnt = g_cnt[e];
    const int m0 = blockIdx.y * 64;
    if (m0 >= cnt) return;
    __shared__ int srow[64];
    __shared__ float As[16][64];
    __shared__ float Bs[16][64];
    const int tid = threadIdx.x;
    if (tid < 64) {
        int m = m0 + tid;
        srow[tid] = (m < cnt) ? g_plist[e * Tn + m] : -1;
    }
    __syncthreads();
    const int n0 = blockIdx.x * 64;
    const int tx = tid & 15, ty = tid >> 4;
    const int arow = tid >> 2, ak = (tid & 3) << 2;
    const int bk = tid >> 4,  bn = (tid & 15) << 2;
    const int slotA = srow[arow];
    const float* Wb = We1 + (size_t)e * KINn * DEHn;
    float acc[4][4] = {};

    for (int k0 = 0; k0 < KINn; k0 += 16) {
        float4 av = make_float4(0.f, 0.f, 0.f, 0.f);
        if (slotA >= 0) {
            if (k0 < Dn) av = *(const float4*)(g_hln  + (size_t)(slotA >> 1) * Dn + k0 + ak);
            else         av = *(const float4*)(g_eemb + (size_t)slotA * DFEn + (k0 - Dn) + ak);
        }
        As[ak + 0][arow] = av.x; As[ak + 1][arow] = av.y;
        As[ak + 2][arow] = av.z; As[ak + 3][arow] = av.w;
        *(float4*)&Bs[bk][bn] = *(const float4*)(Wb + (size_t)(k0 + bk) * DEHn + n0 + bn);
        __syncthreads();
        #pragma unroll
        for (int kk = 0; kk < 16; kk++) {
            float4 a = *(const float4*)&As[kk][ty << 2];
            float4 b = *(const float4*)&Bs[kk][tx << 2];
            float ar[4] = {a.x, a.y, a.z, a.w}, br[4] = {b.x, b.y, b.z, b.w};
            #pragma unroll
            for (int i = 0; i < 4; i++)
                #pragma unroll
                for (int j = 0; j < 4; j++) acc[i][j] = fmaf(ar[i], br[j], acc[i][j]);
        }
        __syncthreads();
    }
    float4 bv = *(const float4*)(be1 + (size_t)e * DEHn + n0 + (tx << 2));
    float bb[4] = {bv.x, bv.y, bv.z, bv.w};
    #pragma unroll
    for (int i = 0; i < 4; i++) {
        int slot = srow[(ty << 2) + i];
        if (slot < 0) continue;
        float4 o;
        o.x = gelu_f(acc[i][0] + bb[0]);
        o.y = gelu_f(acc[i][1] + bb[1]);
        o.z = gelu_f(acc[i][2] + bb[2]);
        o.w = gelu_f(acc[i][3] + bb[3]);
        *(float4*)(g_hh + (size_t)slot * DEHn + n0 + (tx << 2)) = o;
    }
}

// ---------------- K5: expert GEMM2  eo = hh @ We2[e] + be2[e] ----------------
__global__ __launch_bounds__(256) void k_exp_gemm2(
    const float* __restrict__ We2, const float* __restrict__ be2)
{
    const int e = blockIdx.z;
    const int cnt = g_cnt[e];
    const int m0 = blockIdx.y * 64;
    if (m0 >= cnt) return;
    __shared__ int srow[64];
    __shared__ float As[16][64];
    __shared__ float Bs[16][64];
    const int tid = threadIdx.x;
    if (tid < 64) {
        int m = m0 + tid;
        srow[tid] = (m < cnt) ? g_plist[e * Tn + m] : -1;
    }
    __syncthreads();
    const int n0 = blockIdx.x * 64;
    const int tx = tid & 15, ty = tid >> 4;
    const int arow = tid >> 2, ak = (tid & 3) << 2;
    const int bk = tid >> 4,  bn = (tid & 15) << 2;
    const int slotA = srow[arow];
    const float* Wb = We2 + (size_t)e * DEHn * Dn;
    float acc[4][4] = {};

    for (int k0 = 0; k0 < DEHn; k0 += 16) {
        float4 av = make_float4(0.f, 0.f, 0.f, 0.f);
        if (slotA >= 0)
            av = *(const float4*)(g_hh + (size_t)slotA * DEHn + k0 + ak);
        As[ak + 0][arow] = av.x; As[ak + 1][arow] = av.y;
        As[ak + 2][arow] = av.z; As[ak + 3][arow] = av.w;
        *(float4*)&Bs[bk][bn] = *(const float4*)(Wb + (size_t)(k0 + bk) * Dn + n0 + bn);
        __syncthreads();
        #pragma unroll
        for (int kk = 0; kk < 16; kk++) {
            float4 a = *(const float4*)&As[kk][ty << 2];
            float4 b = *(const float4*)&Bs[kk][tx << 2];
            float ar[4] = {a.x, a.y, a.z, a.w}, br[4] = {b.x, b.y, b.z, b.w};
            #pragma unroll
            for (int i = 0; i < 4; i++)
                #pragma unroll
                for (int j = 0; j < 4; j++) acc[i][j] = fmaf(ar[i], br[j], acc[i][j]);
        }
        __syncthreads();
    }
    float4 bv = *(const float4*)(be2 + (size_t)e * Dn + n0 + (tx << 2));
    float bb[4] = {bv.x, bv.y, bv.z, bv.w};
    #pragma unroll
    for (int i = 0; i < 4; i++) {
        int slot = srow[(ty << 2) + i];
        if (slot < 0) continue;
        float4 o;
        o.x = acc[i][0] + bb[0];
        o.y = acc[i][1] + bb[1];
        o.z = acc[i][2] + bb[2];
        o.w = acc[i][3] + bb[3];
        *(float4*)(g_eo + (size_t)slot * Dn + n0 + (tx << 2)) = o;
    }
}

// ---------------- K6: weighted combine + residual ----------------
__global__ __launch_bounds__(256) void k_combine(
    const float* __restrict__ h, float* __restrict__ out)
{
    const int t = blockIdx.x;
    const int i = threadIdx.x;
    const float w0 = g_tokw[t * 2 + 0];
    const float w1 = g_tokw[t * 2 + 1];
    const float4 hv = ((const float4*)(h + (size_t)t * Dn))[i];
    const float4 a  = ((const float4*)(g_eo + (size_t)(t * 2 + 0) * Dn))[i];
    const float4 b  = ((const float4*)(g_eo + (size_t)(t * 2 + 1) * Dn))[i];
    float4 o;
    o.x = hv.x + w0 * a.x + w1 * b.x;
    o.y = hv.y + w0 * a.y + w1 * b.y;
    o.z = hv.z + w0 * a.z + w1 * b.z;
    o.w = hv.w + w0 * a.w + w1 * b.w;
    ((float4*)(out + (size_t)t * Dn))[i] = o;
}

// ---------------- launch ----------------
extern "C" void kernel_launch(void* const* d_in, const int* in_sizes, int n_in,
                              void* d_out, int out_size)
{
    const float* h         = (const float*)d_in[0];
    const float* feat      = (const float*)d_in[1];
    const float* ln_g      = (const float*)d_in[2];
    const float* ln_b      = (const float*)d_in[3];
    const float* Wsf       = (const float*)d_in[4];
    const float* bsf       = (const float*)d_in[5];
    const float* Wr1       = (const float*)d_in[6];
    const float* br1       = (const float*)d_in[7];
    const float* Wr2       = (const float*)d_in[8];
    const float* br2       = (const float*)d_in[9];
    const float* Wef       = (const float*)d_in[10];
    const float* bef       = (const float*)d_in[11];
    const float* We1       = (const float*)d_in[12];
    const float* be1       = (const float*)d_in[13];
    const float* We2       = (const float*)d_in[14];
    const float* be2       = (const float*)d_in[15];
    const int*   stage_idx = (const int*)d_in[16];
    const int*   expert_idx= (const int*)d_in[17];
    float* out = (float*)d_out;

    k_ln<<<Tn, 256>>>(h, feat, ln_g, ln_b, Wsf, bsf, stage_idx);
    k_zero<<<1, 32>>>();
    k_router_gemm<<<dim3(DRHn / 64, Tn / 64), 256>>>(Wr1, br1);
    k_router_topk<<<Tn / 256, 256>>>(Wr2, br2);
    k_eemb<<<Tn * 2, 64>>>(feat, Wef, bef, expert_idx);
    k_exp_gemm1<<<dim3(DEHn / 64, Tn / 64, En), 256>>>(We1, be1);
    k_exp_gemm2<<<dim3(Dn / 64, Tn / 64, En), 256>>>(We2, be2);
    k_combine<<<Tn, 256>>>(h, out);
}

// round 2
// speedup vs baseline: 2.9870x; 2.9870x over previous
#include <cuda_runtime.h>
#include <math.h>

// ---------------- problem constants ----------------
#define Tn    8192          // B*S tokens
#define Dn    1024          // d_model
#define NCOLSn 32
#define FSn   16
#define NEFn  8
#define En    8
#define DFEn  64
#define DRHn  256
#define DEHn  2048
#define KINn  (Dn + DFEn)   // 1088
#define EPSf  1e-5f

// ---------------- scratch ----------------
__device__ float g_hln [Tn * Dn];
__device__ float g_femb[Tn * DFEn];
__device__ float g_hr  [Tn * DRHn];
__device__ int   g_cnt [En];
__device__ int   g_plist[En * Tn];
__device__ int   g_toke[Tn * 2];
__device__ float g_tokw[Tn * 2];
__device__ float g_eemb[Tn * 2 * DFEn];
__device__ float g_hh  [Tn * 2 * DEHn];
__device__ float g_eo  [Tn * 2 * Dn];

__device__ __forceinline__ float gelu_f(float x) {
    float x3 = x * x * x;
    return 0.5f * x * (1.0f + tanhf(0.7978845608028654f * (x + 0.044715f * x3)));
}

__device__ __forceinline__ float tf32r(float f) {
    unsigned u;
    asm("cvt.rna.tf32.f32 %0, %1;" : "=r"(u) : "f"(f));
    return __uint_as_float(u);
}

__device__ __forceinline__ void mma_tf32(float c[4], const unsigned a[4], const unsigned b[2]) {
    asm volatile(
        "mma.sync.aligned.m16n8k8.row.col.f32.tf32.tf32.f32 "
        "{%0,%1,%2,%3}, {%4,%5,%6,%7}, {%8,%9}, {%0,%1,%2,%3};"
        : "+f"(c[0]), "+f"(c[1]), "+f"(c[2]), "+f"(c[3])
        : "r"(a[0]), "r"(a[1]), "r"(a[2]), "r"(a[3]), "r"(b[0]), "r"(b[1]));
}

// ---------------- K1: layernorm + stage-feature embedding ----------------
__global__ __launch_bounds__(256) void k_ln(
    const float* __restrict__ h, const float* __restrict__ feat,
    const float* __restrict__ ln_g, const float* __restrict__ ln_b,
    const float* __restrict__ Wsf, const float* __restrict__ bsf,
    const int* __restrict__ stage_idx)
{
    const int t = blockIdx.x;
    const int tid = threadIdx.x;
    const float4 xv = ((const float4*)(h + (size_t)t * Dn))[tid];

    float s  = xv.x + xv.y + xv.z + xv.w;
    float s2 = xv.x * xv.x + xv.y * xv.y + xv.z * xv.z + xv.w * xv.w;
    #pragma unroll
    for (int o = 16; o > 0; o >>= 1) {
        s  += __shfl_xor_sync(0xffffffffu, s,  o);
        s2 += __shfl_xor_sync(0xffffffffu, s2, o);
    }
    __shared__ float rs[8], rs2[8], stats[2];
    if ((tid & 31) == 0) { rs[tid >> 5] = s; rs2[tid >> 5] = s2; }
    __syncthreads();
    if (tid == 0) {
        float a = 0.f, a2 = 0.f;
        #pragma unroll
        for (int i = 0; i < 8; i++) { a += rs[i]; a2 += rs2[i]; }
        float m = a * (1.0f / Dn);
        stats[0] = m;
        stats[1] = rsqrtf(a2 * (1.0f / Dn) - m * m + EPSf);
    }
    __shared__ float sf[FSn];
    if (tid < FSn) sf[tid] = feat[(size_t)t * NCOLSn + stage_idx[tid]];
    __syncthreads();

    const float m = stats[0], r = stats[1];
    const float4 gv = ((const float4*)ln_g)[tid];
    const float4 bv = ((const float4*)ln_b)[tid];
    float4 o;
    o.x = (xv.x - m) * r * gv.x + bv.x;
    o.y = (xv.y - m) * r * gv.y + bv.y;
    o.z = (xv.z - m) * r * gv.z + bv.z;
    o.w = (xv.w - m) * r * gv.w + bv.w;
    ((float4*)(g_hln + (size_t)t * Dn))[tid] = o;

    if (tid < DFEn) {
        float acc = bsf[tid];
        #pragma unroll
        for (int f = 0; f < FSn; f++) acc = fmaf(sf[f], Wsf[f * DFEn + tid], acc);
        g_femb[(size_t)t * DFEn + tid] = acc;
    }
}

__global__ void k_zero() { if (threadIdx.x < En) g_cnt[threadIdx.x] = 0; }

// ---------------- K2: router GEMM1 (fp32 SIMT — accuracy-critical) ----------------
__global__ __launch_bounds__(256) void k_router_gemm(
    const float* __restrict__ W, const float* __restrict__ bias)
{
    __shared__ float As[16][64];
    __shared__ float Bs[16][64];
    const int m0 = blockIdx.y * 64, n0 = blockIdx.x * 64;
    const int tid = threadIdx.x;
    const int tx = tid & 15, ty = tid >> 4;
    const int arow = tid >> 2, ak = (tid & 3) << 2;
    const int bk = tid >> 4,  bn = (tid & 15) << 2;
    float acc[4][4] = {};

    for (int k0 = 0; k0 < KINn; k0 += 16) {
        float4 av;
        if (k0 < Dn) av = *(const float4*)(g_hln  + (size_t)(m0 + arow) * Dn   + k0 + ak);
        else         av = *(const float4*)(g_femb + (size_t)(m0 + arow) * DFEn + (k0 - Dn) + ak);
        As[ak + 0][arow] = av.x; As[ak + 1][arow] = av.y;
        As[ak + 2][arow] = av.z; As[ak + 3][arow] = av.w;
        *(float4*)&Bs[bk][bn] = *(const float4*)(W + (size_t)(k0 + bk) * DRHn + n0 + bn);
        __syncthreads();
        #pragma unroll
        for (int kk = 0; kk < 16; kk++) {
            float4 a = *(const float4*)&As[kk][ty << 2];
            float4 b = *(const float4*)&Bs[kk][tx << 2];
            float ar[4] = {a.x, a.y, a.z, a.w}, br[4] = {b.x, b.y, b.z, b.w};
            #pragma unroll
            for (int i = 0; i < 4; i++)
                #pragma unroll
                for (int j = 0; j < 4; j++) acc[i][j] = fmaf(ar[i], br[j], acc[i][j]);
        }
        __syncthreads();
    }
    float4 bv = *(const float4*)(bias + n0 + (tx << 2));
    float bb[4] = {bv.x, bv.y, bv.z, bv.w};
    #pragma unroll
    for (int i = 0; i < 4; i++) {
        int m = m0 + (ty << 2) + i;
        float4 o;
        o.x = gelu_f(acc[i][0] + bb[0]);
        o.y = gelu_f(acc[i][1] + bb[1]);
        o.z = gelu_f(acc[i][2] + bb[2]);
        o.w = gelu_f(acc[i][3] + bb[3]);
        *(float4*)(g_hr + (size_t)m * DRHn + n0 + (tx << 2)) = o;
    }
}

// ---------------- K3: logits, top-2 softmax, scatter (warp per token) ----------------
__global__ __launch_bounds__(256) void k_router_topk(
    const float* __restrict__ Wr2, const float* __restrict__ br2)
{
    __shared__ float w2s[DRHn * En];
    for (int i = threadIdx.x; i < DRHn * En; i += 256) w2s[i] = Wr2[i];
    __syncthreads();

    const int w = threadIdx.x >> 5, l = threadIdx.x & 31;
    const int t = blockIdx.x * 8 + w;
    const float* hr = g_hr + (size_t)t * DRHn;

    float lg[En] = {};
    #pragma unroll
    for (int j = 0; j < DRHn / 32; j++) {
        const int k = l + 32 * j;
        const float hv = hr[k];
        #pragma unroll
        for (int e = 0; e < En; e++) lg[e] = fmaf(hv, w2s[k * En + e], lg[e]);
    }
    #pragma unroll
    for (int e = 0; e < En; e++) {
        #pragma unroll
        for (int o = 16; o > 0; o >>= 1) lg[e] += __shfl_xor_sync(0xffffffffu, lg[e], o);
    }
    if (l == 0) {
        #pragma unroll
        for (int e = 0; e < En; e++) lg[e] += br2[e];
        int e1 = 0; float v1 = lg[0];
        #pragma unroll
        for (int e = 1; e < En; e++) if (lg[e] > v1) { v1 = lg[e]; e1 = e; }
        int e2 = -1; float v2 = -1e30f;
        #pragma unroll
        for (int e = 0; e < En; e++) if (e != e1 && lg[e] > v2) { v2 = lg[e]; e2 = e; }
        float z = expf(v2 - v1);
        float w1 = 1.0f / (1.0f + z);
        float w2 = z / (1.0f + z);
        g_toke[t * 2 + 0] = e1; g_toke[t * 2 + 1] = e2;
        g_tokw[t * 2 + 0] = w1; g_tokw[t * 2 + 1] = w2;
        int p1 = atomicAdd(&g_cnt[e1], 1); g_plist[e1 * Tn + p1] = t * 2;
        int p2 = atomicAdd(&g_cnt[e2], 1); g_plist[e2 * Tn + p2] = t * 2 + 1;
    }
}

// ---------------- K3b: expert feature embedding per slot ----------------
__global__ __launch_bounds__(64) void k_eemb(
    const float* __restrict__ feat, const float* __restrict__ Wef,
    const float* __restrict__ bef, const int* __restrict__ expert_idx)
{
    const int slot = blockIdx.x;
    const int e = g_toke[slot];
    const int t = slot >> 1;
    __shared__ float fv[NEFn];
    if (threadIdx.x < NEFn) {
        int col = expert_idx[e * NEFn + threadIdx.x];
        fv[threadIdx.x] = feat[(size_t)t * NCOLSn + col];
    }
    __syncthreads();
    const int d = threadIdx.x;
    float acc = bef[e * DFEn + d];
    #pragma unroll
    for (int f = 0; f < NEFn; f++)
        acc = fmaf(fv[f], Wef[((size_t)e * NEFn + f) * DFEn + d], acc);
    g_eemb[(size_t)slot * DFEn + d] = acc;
}

// ================= tf32 tensor-core expert GEMMs =================
// Tile: 128(M) x 128(N) x 16(K), 256 threads = 8 warps (2x4), warp tile 64x32.
// A gathered by slot list; smem A [128][20] (row-major, pad 4), B [16][136] (pad 8).

#define ASTRIDE 20
#define BSTRIDE 136

// ---------------- K4: expert GEMM1  hh = gelu([hln|eemb] @ We1[e] + be1[e]) ----------------
__global__ __launch_bounds__(256) void k_exp_gemm1_tc(
    const float* __restrict__ We1, const float* __restrict__ be1)
{
    const int e = blockIdx.z;
    const int cnt = g_cnt[e];
    const int m0 = blockIdx.y * 128;
    if (m0 >= cnt) return;
    const int n0 = blockIdx.x * 128;

    __shared__ int   srow[128];
    __shared__ float As[2][128][ASTRIDE];
    __shared__ float Bs[2][16][BSTRIDE];

    const int tid = threadIdx.x;
    if (tid < 128) {
        int m = m0 + tid;
        srow[tid] = (m < cnt) ? g_plist[e * Tn + m] : -1;
    }
    __syncthreads();

    const int warp = tid >> 5, lane = tid & 31;
    const int wm = (warp >> 2) * 64, wn = (warp & 3) * 32;
    const int gid = lane >> 2, tig = lane & 3;

    const int arow = tid >> 1;
    const int akq  = (tid & 1) * 8;
    const int aslot = srow[arow];
    const int atok  = aslot >> 1;
    const int bkr = tid >> 4;
    const int bnq = (tid & 15) * 8;
    const float* Wb = We1 + (size_t)e * KINn * DEHn;

    float acc[4][4][4];
    #pragma unroll
    for (int i = 0; i < 4; i++)
        #pragma unroll
        for (int j = 0; j < 4; j++)
            #pragma unroll
            for (int q = 0; q < 4; q++) acc[i][j][q] = 0.f;

    float4 av0, av1, bv0, bv1;

    // --- tile load helpers (inline) ---
    #define LOAD_TILE_G1(K0)                                                        \
    {                                                                               \
        if (aslot >= 0) {                                                           \
            const float* p = ((K0) < Dn)                                            \
                ? (g_hln  + (size_t)atok  * Dn   + (K0) + akq)                      \
                : (g_eemb + (size_t)aslot * DFEn + ((K0) - Dn) + akq);              \
            av0 = *(const float4*)p; av1 = *(const float4*)(p + 4);                 \
        } else { av0 = av1 = make_float4(0.f, 0.f, 0.f, 0.f); }                     \
        const float* q = Wb + (size_t)((K0) + bkr) * DEHn + n0 + bnq;               \
        bv0 = *(const float4*)q; bv1 = *(const float4*)(q + 4);                     \
    }

    #define STORE_TILE(BUF)                                                         \
    {                                                                               \
        float4 t0 = make_float4(tf32r(av0.x), tf32r(av0.y), tf32r(av0.z), tf32r(av0.w)); \
        float4 t1 = make_float4(tf32r(av1.x), tf32r(av1.y), tf32r(av1.z), tf32r(av1.w)); \
        *(float4*)&As[BUF][arow][akq]     = t0;                                     \
        *(float4*)&As[BUF][arow][akq + 4] = t1;                                     \
        float4 u0 = make_float4(tf32r(bv0.x), tf32r(bv0.y), tf32r(bv0.z), tf32r(bv0.w)); \
        float4 u1 = make_float4(tf32r(bv1.x), tf32r(bv1.y), tf32r(bv1.z), tf32r(bv1.w)); \
        *(float4*)&Bs[BUF][bkr][bnq]     = u0;                                      \
        *(float4*)&Bs[BUF][bkr][bnq + 4] = u1;                                      \
    }

    #define COMPUTE_TILE(BUF)                                                       \
    {                                                                               \
        _Pragma("unroll")                                                           \
        for (int ks = 0; ks < 2; ks++) {                                            \
            const int k8 = ks * 8;                                                  \
            unsigned a[4][4], b[4][2];                                              \
            _Pragma("unroll")                                                       \
            for (int mi = 0; mi < 4; mi++) {                                        \
                const float* ap = &As[BUF][wm + mi * 16 + gid][k8 + tig];           \
                a[mi][0] = __float_as_uint(ap[0]);                                  \
                a[mi][1] = __float_as_uint(ap[8 * ASTRIDE]);                        \
                a[mi][2] = __float_as_uint(ap[4]);                                  \
                a[mi][3] = __float_as_uint(ap[8 * ASTRIDE + 4]);                    \
            }                                                                       \
            _Pragma("unroll")                                                       \
            for (int ni = 0; ni < 4; ni++) {                                        \
                b[ni][0] = __float_as_uint(Bs[BUF][k8 + tig][wn + ni * 8 + gid]);   \
                b[ni][1] = __float_as_uint(Bs[BUF][k8 + 4 + tig][wn + ni * 8 + gid]);\
            }                                                                       \
            _Pragma("unroll")                                                       \
            for (int mi = 0; mi < 4; mi++)                                          \
                _Pragma("unroll")                                                   \
                for (int ni = 0; ni < 4; ni++)                                      \
                    mma_tf32(acc[mi][ni], a[mi], b[ni]);                            \
        }                                                                           \
    }

    const int nk = KINn / 16;  // 68
    LOAD_TILE_G1(0)
    STORE_TILE(0)
    __syncthreads();
    int buf = 0;
    for (int kt = 0; kt < nk; kt++) {
        if (kt + 1 < nk) { LOAD_TILE_G1((kt + 1) * 16) }
        COMPUTE_TILE(buf)
        if (kt + 1 < nk) { STORE_TILE(buf ^ 1) }
        __syncthreads();
        buf ^= 1;
    }

    // epilogue: bias + gelu -> g_hh
    #pragma unroll
    for (int ni = 0; ni < 4; ni++) {
        const int c = n0 + wn + ni * 8 + 2 * tig;
        const float2 bb = *(const float2*)(be1 + (size_t)e * DEHn + c);
        #pragma unroll
        for (int mi = 0; mi < 4; mi++) {
            const int r0 = wm + mi * 16 + gid;
            const int s0 = srow[r0], s1 = srow[r0 + 8];
            if (s0 >= 0) {
                float2 o;
                o.x = gelu_f(acc[mi][ni][0] + bb.x);
                o.y = gelu_f(acc[mi][ni][1] + bb.y);
                *(float2*)(g_hh + (size_t)s0 * DEHn + c) = o;
            }
            if (s1 >= 0) {
                float2 o;
                o.x = gelu_f(acc[mi][ni][2] + bb.x);
                o.y = gelu_f(acc[mi][ni][3] + bb.y);
                *(float2*)(g_hh + (size_t)s1 * DEHn + c) = o;
            }
        }
    }
    #undef LOAD_TILE_G1
    #undef STORE_TILE
    #undef COMPUTE_TILE
}

// ---------------- K5: expert GEMM2  eo = hh @ We2[e] + be2[e] ----------------
__global__ __launch_bounds__(256) void k_exp_gemm2_tc(
    const float* __restrict__ We2, const float* __restrict__ be2)
{
    const int e = blockIdx.z;
    const int cnt = g_cnt[e];
    const int m0 = blockIdx.y * 128;
    if (m0 >= cnt) return;
    const int n0 = blockIdx.x * 128;

    __shared__ int   srow[128];
    __shared__ float As[2][128][ASTRIDE];
    __shared__ float Bs[2][16][BSTRIDE];

    const int tid = threadIdx.x;
    if (tid < 128) {
        int m = m0 + tid;
        srow[tid] = (m < cnt) ? g_plist[e * Tn + m] : -1;
    }
    __syncthreads();

    const int warp = tid >> 5, lane = tid & 31;
    const int wm = (warp >> 2) * 64, wn = (warp & 3) * 32;
    const int gid = lane >> 2, tig = lane & 3;

    const int arow = tid >> 1;
    const int akq  = (tid & 1) * 8;
    const int aslot = srow[arow];
    const int bkr = tid >> 4;
    const int bnq = (tid & 15) * 8;
    const float* Wb = We2 + (size_t)e * DEHn * Dn;

    float acc[4][4][4];
    #pragma unroll
    for (int i = 0; i < 4; i++)
        #pragma unroll
        for (int j = 0; j < 4; j++)
            #pragma unroll
            for (int q = 0; q < 4; q++) acc[i][j][q] = 0.f;

    float4 av0, av1, bv0, bv1;

    #define LOAD_TILE_G2(K0)                                                        \
    {                                                                               \
        if (aslot >= 0) {                                                           \
            const float* p = g_hh + (size_t)aslot * DEHn + (K0) + akq;              \
            av0 = *(const float4*)p; av1 = *(const float4*)(p + 4);                 \
        } else { av0 = av1 = make_float4(0.f, 0.f, 0.f, 0.f); }                     \
        const float* q = Wb + (size_t)((K0) + bkr) * Dn + n0 + bnq;                 \
        bv0 = *(const float4*)q; bv1 = *(const float4*)(q + 4);                     \
    }

    #define STORE_TILE(BUF)                                                         \
    {                                                                               \
        float4 t0 = make_float4(tf32r(av0.x), tf32r(av0.y), tf32r(av0.z), tf32r(av0.w)); \
        float4 t1 = make_float4(tf32r(av1.x), tf32r(av1.y), tf32r(av1.z), tf32r(av1.w)); \
        *(float4*)&As[BUF][arow][akq]     = t0;                                     \
        *(float4*)&As[BUF][arow][akq + 4] = t1;                                     \
        float4 u0 = make_float4(tf32r(bv0.x), tf32r(bv0.y), tf32r(bv0.z), tf32r(bv0.w)); \
        float4 u1 = make_float4(tf32r(bv1.x), tf32r(bv1.y), tf32r(bv1.z), tf32r(bv1.w)); \
        *(float4*)&Bs[BUF][bkr][bnq]     = u0;                                      \
        *(float4*)&Bs[BUF][bkr][bnq + 4] = u1;                                      \
    }

    #define COMPUTE_TILE(BUF)                                                       \
    {                                                                               \
        _Pragma("unroll")                                                           \
        for (int ks = 0; ks < 2; ks++) {                                            \
            const int k8 = ks * 8;                                                  \
            unsigned a[4][4], b[4][2];                                              \
            _Pragma("unroll")                                                       \
            for (int mi = 0; mi < 4; mi++) {                                        \
                const float* ap = &As[BUF][wm + mi * 16 + gid][k8 + tig];           \
                a[mi][0] = __float_as_uint(ap[0]);                                  \
                a[mi][1] = __float_as_uint(ap[8 * ASTRIDE]);                        \
                a[mi][2] = __float_as_uint(ap[4]);                                  \
                a[mi][3] = __float_as_uint(ap[8 * ASTRIDE + 4]);                    \
            }                                                                       \
            _Pragma("unroll")                                                       \
            for (int ni = 0; ni < 4; ni++) {                                        \
                b[ni][0] = __float_as_uint(Bs[BUF][k8 + tig][wn + ni * 8 + gid]);   \
                b[ni][1] = __float_as_uint(Bs[BUF][k8 + 4 + tig][wn + ni * 8 + gid]);\
            }                                                                       \
            _Pragma("unroll")                                                       \
            for (int mi = 0; mi < 4; mi++)                                          \
                _Pragma("unroll")                                                   \
                for (int ni = 0; ni < 4; ni++)                                      \
                    mma_tf32(acc[mi][ni], a[mi], b[ni]);                            \
        }                                                                           \
    }

    const int nk = DEHn / 16;  // 128
    LOAD_TILE_G2(0)
    STORE_TILE(0)
    __syncthreads();
    int buf = 0;
    for (int kt = 0; kt < nk; kt++) {
        if (kt + 1 < nk) { LOAD_TILE_G2((kt + 1) * 16) }
        COMPUTE_TILE(buf)
        if (kt + 1 < nk) { STORE_TILE(buf ^ 1) }
        __syncthreads();
        buf ^= 1;
    }

    // epilogue: bias -> g_eo
    #pragma unroll
    for (int ni = 0; ni < 4; ni++) {
        const int c = n0 + wn + ni * 8 + 2 * tig;
        const float2 bb = *(const float2*)(be2 + (size_t)e * Dn + c);
        #pragma unroll
        for (int mi = 0; mi < 4; mi++) {
            const int r0 = wm + mi * 16 + gid;
            const int s0 = srow[r0], s1 = srow[r0 + 8];
            if (s0 >= 0) {
                float2 o;
                o.x = acc[mi][ni][0] + bb.x;
                o.y = acc[mi][ni][1] + bb.y;
                *(float2*)(g_eo + (size_t)s0 * Dn + c) = o;
            }
            if (s1 >= 0) {
                float2 o;
                o.x = acc[mi][ni][2] + bb.x;
                o.y = acc[mi][ni][3] + bb.y;
                *(float2*)(g_eo + (size_t)s1 * Dn + c) = o;
            }
        }
    }
    #undef LOAD_TILE_G2
    #undef STORE_TILE
    #undef COMPUTE_TILE
}

// ---------------- K6: weighted combine + residual ----------------
__global__ __launch_bounds__(256) void k_combine(
    const float* __restrict__ h, float* __restrict__ out)
{
    const int t = blockIdx.x;
    const int i = threadIdx.x;
    const float w0 = g_tokw[t * 2 + 0];
    const float w1 = g_tokw[t * 2 + 1];
    const float4 hv = ((const float4*)(h + (size_t)t * Dn))[i];
    const float4 a  = ((const float4*)(g_eo + (size_t)(t * 2 + 0) * Dn))[i];
    const float4 b  = ((const float4*)(g_eo + (size_t)(t * 2 + 1) * Dn))[i];
    float4 o;
    o.x = hv.x + w0 * a.x + w1 * b.x;
    o.y = hv.y + w0 * a.y + w1 * b.y;
    o.z = hv.z + w0 * a.z + w1 * b.z;
    o.w = hv.w + w0 * a.w + w1 * b.w;
    ((float4*)(out + (size_t)t * Dn))[i] = o;
}

// ---------------- launch ----------------
extern "C" void kernel_launch(void* const* d_in, const int* in_sizes, int n_in,
                              void* d_out, int out_size)
{
    const float* h         = (const float*)d_in[0];
    const float* feat      = (const float*)d_in[1];
    const float* ln_g      = (const float*)d_in[2];
    const float* ln_b      = (const float*)d_in[3];
    const float* Wsf       = (const float*)d_in[4];
    const float* bsf       = (const float*)d_in[5];
    const float* Wr1       = (const float*)d_in[6];
    const float* br1       = (const float*)d_in[7];
    const float* Wr2       = (const float*)d_in[8];
    const float* br2       = (const float*)d_in[9];
    const float* Wef       = (const float*)d_in[10];
    const float* bef       = (const float*)d_in[11];
    const float* We1       = (const float*)d_in[12];
    const float* be1       = (const float*)d_in[13];
    const float* We2       = (const float*)d_in[14];
    const float* be2       = (const float*)d_in[15];
    const int*   stage_idx = (const int*)d_in[16];
    const int*   expert_idx= (const int*)d_in[17];
    float* out = (float*)d_out;

    k_ln<<<Tn, 256>>>(h, feat, ln_g, ln_b, Wsf, bsf, stage_idx);
    k_zero<<<1, 32>>>();
    k_router_gemm<<<dim3(DRHn / 64, Tn / 64), 256>>>(Wr1, br1);
    k_router_topk<<<Tn / 8, 256>>>(Wr2, br2);
    k_eemb<<<Tn * 2, 64>>>(feat, Wef, bef, expert_idx);
    k_exp_gemm1_tc<<<dim3(DEHn / 128, Tn / 128, En), 256>>>(We1, be1);
    k_exp_gemm2_tc<<<dim3(Dn / 128, Tn / 128, En), 256>>>(We2, be2);
    k_combine<<<Tn, 256>>>(h, out);
}

// round 6
// speedup vs baseline: 4.4907x; 1.5034x over previous
#include <cuda_runtime.h>
#include <cuda_fp16.h>
#include <math.h>
#include <stdint.h>

// ---------------- problem constants ----------------
#define Tn    8192          // B*S tokens
#define Dn    1024          // d_model
#define NCOLSn 32
#define FSn   16
#define NEFn  8
#define En    8
#define DFEn  64
#define DRHn  256
#define DEHn  2048
#define KINn  (Dn + DFEn)   // 1088
#define EPSf  1e-5f

// ---------------- scratch ----------------
__device__ __half g_hln_h [Tn * Dn];                 // 16 MB  hi
__device__ __half g_hln_l [Tn * Dn];                 // 16 MB  lo residual (router only)
__device__ __half g_femb_h[Tn * DFEn];
__device__ __half g_femb_l[Tn * DFEn];
__device__ float  g_hr    [Tn * DRHn];               //  8 MB
__device__ int    g_cnt   [En];
__device__ int    g_plist [En * Tn];
__device__ int    g_toke  [Tn * 2];
__device__ float  g_tokw  [Tn * 2];
__device__ __half g_eemb_h[Tn * 2 * DFEn];
__device__ __half g_hh_h  [Tn * 2 * DEHn];           // 64 MB
__device__ float  g_eo    [Tn * 2 * Dn];             // 64 MB
__device__ __half g_We1t_h[En * (size_t)KINn * DEHn]; // 36 MB  [e][n][k]
__device__ __half g_We2t_h[En * (size_t)DEHn * Dn];   // 32 MB  [e][n][k]
__device__ __half g_Wr1t_h[(size_t)KINn * DRHn];      // [n][k] hi
__device__ __half g_Wr1t_l[(size_t)KINn * DRHn];      // [n][k] lo

__device__ __forceinline__ float gelu_f(float x) {
    float x3 = x * x * x;
    return 0.5f * x * (1.0f + tanhf(0.7978845608028654f * (x + 0.044715f * x3)));
}

__device__ __forceinline__ void mma_f16(float c[4], const unsigned a[4], const unsigned b[2]) {
    asm volatile(
        "mma.sync.aligned.m16n8k16.row.col.f32.f16.f16.f32 "
        "{%0,%1,%2,%3}, {%4,%5,%6,%7}, {%8,%9}, {%0,%1,%2,%3};"
        : "+f"(c[0]), "+f"(c[1]), "+f"(c[2]), "+f"(c[3])
        : "r"(a[0]), "r"(a[1]), "r"(a[2]), "r"(a[3]), "r"(b[0]), "r"(b[1]));
}

// ---------------- K0a: weight transpose+cvt  W[e][K][N] f32 -> Wt[e][N][K] f16 ----------------
__global__ __launch_bounds__(256) void k_transpose_h(
    const float* __restrict__ W, __half* __restrict__ Wt, int K, int N)
{
    __shared__ float tile[32][33];
    const int e = blockIdx.z;
    const float* Wp  = W  + (size_t)e * K * N;
    __half*      Wtp = Wt + (size_t)e * K * N;
    int x = blockIdx.x * 32 + threadIdx.x;   // n
    int y = blockIdx.y * 32 + threadIdx.y;   // k
    #pragma unroll
    for (int i = 0; i < 32; i += 8)
        tile[threadIdx.y + i][threadIdx.x] = Wp[(size_t)(y + i) * N + x];
    __syncthreads();
    x = blockIdx.y * 32 + threadIdx.x;       // k
    y = blockIdx.x * 32 + threadIdx.y;       // n
    #pragma unroll
    for (int i = 0; i < 32; i += 8)
        Wtp[(size_t)(y + i) * K + x] = __float2half(tile[threadIdx.x][threadIdx.y + i]);
}

// ---------------- K0b: transpose with hi/lo split (router W1) ----------------
__global__ __launch_bounds__(256) void k_transpose_hl(
    const float* __restrict__ W, __half* __restrict__ Wth, __half* __restrict__ Wtl,
    int K, int N)
{
    __shared__ float tile[32][33];
    const float* Wp = W;
    int x = blockIdx.x * 32 + threadIdx.x;   // n
    int y = blockIdx.y * 32 + threadIdx.y;   // k
    #pragma unroll
    for (int i = 0; i < 32; i += 8)
        tile[threadIdx.y + i][threadIdx.x] = Wp[(size_t)(y + i) * N + x];
    __syncthreads();
    x = blockIdx.y * 32 + threadIdx.x;       // k
    y = blockIdx.x * 32 + threadIdx.y;       // n
    #pragma unroll
    for (int i = 0; i < 32; i += 8) {
        float v = tile[threadIdx.x][threadIdx.y + i];
        __half hi = __float2half(v);
        __half lo = __float2half(v - __half2float(hi));
        Wth[(size_t)(y + i) * K + x] = hi;
        Wtl[(size_t)(y + i) * K + x] = lo;
    }
}

// ---------------- K1: layernorm + stage-feature embedding (+ zero cnt) ----------------
__global__ __launch_bounds__(256) void k_ln(
    const float* __restrict__ h, const float* __restrict__ feat,
    const float* __restrict__ ln_g, const float* __restrict__ ln_b,
    const float* __restrict__ Wsf, const float* __restrict__ bsf,
    const int* __restrict__ stage_idx)
{
    const int t = blockIdx.x;
    const int tid = threadIdx.x;
    if (blockIdx.x == 0 && tid < En) g_cnt[tid] = 0;
    const float4 xv = ((const float4*)(h + (size_t)t * Dn))[tid];

    float s  = xv.x + xv.y + xv.z + xv.w;
    float s2 = xv.x * xv.x + xv.y * xv.y + xv.z * xv.z + xv.w * xv.w;
    #pragma unroll
    for (int o = 16; o > 0; o >>= 1) {
        s  += __shfl_xor_sync(0xffffffffu, s,  o);
        s2 += __shfl_xor_sync(0xffffffffu, s2, o);
    }
    __shared__ float rs[8], rs2[8], stats[2];
    if ((tid & 31) == 0) { rs[tid >> 5] = s; rs2[tid >> 5] = s2; }
    __syncthreads();
    if (tid == 0) {
        float a = 0.f, a2 = 0.f;
        #pragma unroll
        for (int i = 0; i < 8; i++) { a += rs[i]; a2 += rs2[i]; }
        float m = a * (1.0f / Dn);
        stats[0] = m;
        stats[1] = rsqrtf(a2 * (1.0f / Dn) - m * m + EPSf);
    }
    __shared__ float sf[FSn];
    if (tid < FSn) sf[tid] = feat[(size_t)t * NCOLSn + stage_idx[tid]];
    __syncthreads();

    const float m = stats[0], r = stats[1];
    const float4 gv = ((const float4*)ln_g)[tid];
    const float4 bv = ((const float4*)ln_b)[tid];
    float o[4];
    o[0] = (xv.x - m) * r * gv.x + bv.x;
    o[1] = (xv.y - m) * r * gv.y + bv.y;
    o[2] = (xv.z - m) * r * gv.z + bv.z;
    o[3] = (xv.w - m) * r * gv.w + bv.w;
    __half2* dh = (__half2*)(g_hln_h + (size_t)t * Dn);
    __half2* dl = (__half2*)(g_hln_l + (size_t)t * Dn);
    #pragma unroll
    for (int q = 0; q < 2; q++) {
        __half2 hi = __floats2half2_rn(o[2 * q], o[2 * q + 1]);
        float2 hif = __half22float2(hi);
        __half2 lo = __floats2half2_rn(o[2 * q] - hif.x, o[2 * q + 1] - hif.y);
        dh[tid * 2 + q] = hi;
        dl[tid * 2 + q] = lo;
    }

    if (tid < DFEn) {
        float acc = bsf[tid];
        #pragma unroll
        for (int f = 0; f < FSn; f++) acc = fmaf(sf[f], Wsf[f * DFEn + tid], acc);
        __half hi = __float2half(acc);
        g_femb_h[(size_t)t * DFEn + tid] = hi;
        g_femb_l[(size_t)t * DFEn + tid] = __float2half(acc - __half2float(hi));
    }
}

// ================= fp16 mma GEMM core (macros shared by kernels) =================
// Tile 128M x 128N x 16K, 256 threads = 8 warps (2x4), warp tile 64x32.
// smem: rows [128][24] half (pad 8 halves -> conflict-free fragment LDS).

#define MMA_DECL                                                                  \
    const int tid = threadIdx.x;                                                  \
    const int warp = tid >> 5, lane = tid & 31;                                   \
    const int wm = (warp >> 2) * 64, wn = (warp & 3) * 32;                        \
    const int gid = lane >> 2, tig = lane & 3;                                    \
    const int arow = tid >> 1, achk = (tid & 1) * 8;                              \
    float acc[4][4][4];                                                           \
    _Pragma("unroll") for (int i = 0; i < 4; i++)                                 \
    _Pragma("unroll") for (int j = 0; j < 4; j++)                                 \
    _Pragma("unroll") for (int q = 0; q < 4; q++) acc[i][j][q] = 0.f;

#define MMA_FRAG_A(dst, SM, BUF)                                                  \
    _Pragma("unroll")                                                             \
    for (int mi = 0; mi < 4; mi++) {                                              \
        const int r0 = wm + mi * 16 + gid;                                        \
        dst[mi][0] = *(const unsigned*)&SM[BUF][r0][2 * tig];                     \
        dst[mi][1] = *(const unsigned*)&SM[BUF][r0 + 8][2 * tig];                 \
        dst[mi][2] = *(const unsigned*)&SM[BUF][r0][2 * tig + 8];                 \
        dst[mi][3] = *(const unsigned*)&SM[BUF][r0 + 8][2 * tig + 8];             \
    }

#define MMA_FRAG_B(dst, SM, BUF)                                                  \
    _Pragma("unroll")                                                             \
    for (int ni = 0; ni < 4; ni++) {                                              \
        const int nr = wn + ni * 8 + gid;                                         \
        dst[ni][0] = *(const unsigned*)&SM[BUF][nr][2 * tig];                     \
        dst[ni][1] = *(const unsigned*)&SM[BUF][nr][2 * tig + 8];                 \
    }

#define MMA_ALL(afrag, bfrag)                                                     \
    _Pragma("unroll")                                                             \
    for (int mi = 0; mi < 4; mi++)                                                \
        _Pragma("unroll")                                                         \
        for (int ni = 0; ni < 4; ni++)                                            \
            mma_f16(acc[mi][ni], afrag[mi], bfrag[ni]);

// ---------------- router GEMM1 (split-fp16, fp32-class accuracy) ----------------
__global__ __launch_bounds__(256) void k_router_gemm_split(const float* __restrict__ bias)
{
    __shared__ __half Ah[2][128][24];
    __shared__ __half Al[2][128][24];
    __shared__ __half Bh[2][128][24];
    __shared__ __half Bl[2][128][24];
    const int m0 = blockIdx.y * 128, n0 = blockIdx.x * 128;
    MMA_DECL
    uint4 rah, ral, rbh, rbl;

    #define RLOAD(K0)                                                             \
    {                                                                             \
        const int k = (K0) + achk;                                                \
        if (k < Dn) {                                                             \
            rah = *(const uint4*)(g_hln_h + (size_t)(m0 + arow) * Dn + k);        \
            ral = *(const uint4*)(g_hln_l + (size_t)(m0 + arow) * Dn + k);        \
        } else {                                                                  \
            rah = *(const uint4*)(g_femb_h + (size_t)(m0 + arow) * DFEn + (k - Dn)); \
            ral = *(const uint4*)(g_femb_l + (size_t)(m0 + arow) * DFEn + (k - Dn)); \
        }                                                                         \
        rbh = *(const uint4*)(g_Wr1t_h + (size_t)(n0 + arow) * KINn + k);         \
        rbl = *(const uint4*)(g_Wr1t_l + (size_t)(n0 + arow) * KINn + k);         \
    }
    #define RSTORE(BUF)                                                           \
    {                                                                             \
        *(uint4*)&Ah[BUF][arow][achk] = rah;                                      \
        *(uint4*)&Al[BUF][arow][achk] = ral;                                      \
        *(uint4*)&Bh[BUF][arow][achk] = rbh;                                      \
        *(uint4*)&Bl[BUF][arow][achk] = rbl;                                      \
    }
    #define RCOMP(BUF)                                                            \
    {                                                                             \
        unsigned ah[4][4], al[4][4], bh[4][2], bl[4][2];                          \
        MMA_FRAG_A(ah, Ah, BUF)                                                   \
        MMA_FRAG_A(al, Al, BUF)                                                   \
        MMA_FRAG_B(bh, Bh, BUF)                                                   \
        MMA_FRAG_B(bl, Bl, BUF)                                                   \
        MMA_ALL(ah, bh)                                                           \
        MMA_ALL(ah, bl)                                                           \
        MMA_ALL(al, bh)                                                           \
    }

    const int nk = KINn / 16;  // 68
    RLOAD(0)
    RSTORE(0)
    __syncthreads();
    int buf = 0;
    for (int kt = 0; kt < nk; kt++) {
        if (kt + 1 < nk) RLOAD((kt + 1) * 16)
        RCOMP(buf)
        if (kt + 1 < nk) RSTORE(buf ^ 1)
        __syncthreads();
        buf ^= 1;
    }
    #undef RLOAD
    #undef RSTORE
    #undef RCOMP

    #pragma unroll
    for (int ni = 0; ni < 4; ni++) {
        const int c = n0 + wn + ni * 8 + 2 * tig;
        const float2 bb = *(const float2*)(bias + c);
        #pragma unroll
        for (int mi = 0; mi < 4; mi++) {
            const int r0 = m0 + wm + mi * 16 + gid;
            float2 o0, o1;
            o0.x = gelu_f(acc[mi][ni][0] + bb.x);
            o0.y = gelu_f(acc[mi][ni][1] + bb.y);
            o1.x = gelu_f(acc[mi][ni][2] + bb.x);
            o1.y = gelu_f(acc[mi][ni][3] + bb.y);
            *(float2*)(g_hr + (size_t)r0 * DRHn + c)       = o0;
            *(float2*)(g_hr + (size_t)(r0 + 8) * DRHn + c) = o1;
        }
    }
}

// ---------------- K3: logits (fp32), top-2 softmax, scatter + fused eemb ----------------
__global__ __launch_bounds__(256) void k_router_topk(
    const float* __restrict__ Wr2, const float* __restrict__ br2,
    const float* __restrict__ feat, const float* __restrict__ Wef,
    const float* __restrict__ bef, const int* __restrict__ expert_idx)
{
    __shared__ float w2s[DRHn * En];
    __shared__ float wefs[En * NEFn * DFEn];
    __shared__ float befs[En * DFEn];
    __shared__ int   eidx[En * NEFn];
    for (int i = threadIdx.x; i < DRHn * En; i += 256) w2s[i] = Wr2[i];
    for (int i = threadIdx.x; i < En * NEFn * DFEn; i += 256) wefs[i] = Wef[i];
    for (int i = threadIdx.x; i < En * DFEn; i += 256) befs[i] = bef[i];
    if (threadIdx.x < En * NEFn) eidx[threadIdx.x] = expert_idx[threadIdx.x];
    __syncthreads();

    const int w = threadIdx.x >> 5, l = threadIdx.x & 31;
    const int t = blockIdx.x * 8 + w;
    const float* hr = g_hr + (size_t)t * DRHn;

    float lg[En] = {};
    #pragma unroll
    for (int j = 0; j < DRHn / 32; j++) {
        const int k = l + 32 * j;
        const float hv = hr[k];
        #pragma unroll
        for (int e = 0; e < En; e++) lg[e] = fmaf(hv, w2s[k * En + e], lg[e]);
    }
    #pragma unroll
    for (int e = 0; e < En; e++) {
        #pragma unroll
        for (int o = 16; o > 0; o >>= 1) lg[e] += __shfl_xor_sync(0xffffffffu, lg[e], o);
    }
    int e1 = 0, e2 = -1;
    if (l == 0) {
        #pragma unroll
        for (int e = 0; e < En; e++) lg[e] += br2[e];
        float v1 = lg[0];
        #pragma unroll
        for (int e = 1; e < En; e++) if (lg[e] > v1) { v1 = lg[e]; e1 = e; }
        float v2 = -1e30f;
        #pragma unroll
        for (int e = 0; e < En; e++) if (e != e1 && lg[e] > v2) { v2 = lg[e]; e2 = e; }
        float z = expf(v2 - v1);
        float w1 = 1.0f / (1.0f + z);
        float w2 = z / (1.0f + z);
        g_toke[t * 2 + 0] = e1; g_toke[t * 2 + 1] = e2;
        g_tokw[t * 2 + 0] = w1; g_tokw[t * 2 + 1] = w2;
        int p1 = atomicAdd(&g_cnt[e1], 1); g_plist[e1 * Tn + p1] = t * 2;
        int p2 = atomicAdd(&g_cnt[e2], 1); g_plist[e2 * Tn + p2] = t * 2 + 1;
    }
    e1 = __shfl_sync(0xffffffffu, e1, 0);
    e2 = __shfl_sync(0xffffffffu, e2, 0);

    // fused eemb for both slots: each lane handles dims l and l+32
    #pragma unroll
    for (int s = 0; s < 2; s++) {
        const int e = s ? e2 : e1;
        float fv[NEFn];
        #pragma unroll
        for (int f = 0; f < NEFn; f++)
            fv[f] = feat[(size_t)t * NCOLSn + eidx[e * NEFn + f]];
        #pragma unroll
        for (int half_d = 0; half_d < 2; half_d++) {
            const int d = l + half_d * 32;
            float acc = befs[e * DFEn + d];
            #pragma unroll
            for (int f = 0; f < NEFn; f++)
                acc = fmaf(fv[f], wefs[(e * NEFn + f) * DFEn + d], acc);
            g_eemb_h[(size_t)(t * 2 + s) * DFEn + d] = __float2half(acc);
        }
    }
}

// ---------------- expert GEMMs (gathered rows), fp16 mma ----------------
template<bool G1>
__global__ __launch_bounds__(256) void k_exp_gemm_h(
    const __half* __restrict__ Wt, const float* __restrict__ bias)
{
    constexpr int KD  = G1 ? KINn : DEHn;   // 1088 / 2048
    constexpr int NK  = KD / 16;            // 68 / 128
    constexpr int DST = G1 ? DEHn : Dn;     // output width
    const int e = blockIdx.z;
    const int cnt = g_cnt[e];
    const int m0 = blockIdx.x * 128;
    if (m0 >= cnt) return;
    const int n0 = blockIdx.y * 128;

    __shared__ int    srow[128];
    __shared__ __half As[2][128][24];
    __shared__ __half Bs[2][128][24];

    if (threadIdx.x < 128) {
        int m = m0 + threadIdx.x;
        srow[threadIdx.x] = (m < cnt) ? g_plist[e * Tn + m] : -1;
    }
    __syncthreads();

    MMA_DECL
    uint4 areg, breg;
    const int aslot = srow[arow];
    const __half* Wte = Wt + (size_t)e * KD * DST;

    #define ELOAD(K0)                                                             \
    {                                                                             \
        if (aslot >= 0) {                                                         \
            const int k = (K0) + achk;                                            \
            const __half* p;                                                      \
            if (G1) p = (k < Dn) ? (g_hln_h + (size_t)(aslot >> 1) * Dn + k)      \
                                 : (g_eemb_h + (size_t)aslot * DFEn + (k - Dn));  \
            else    p = g_hh_h + (size_t)aslot * DEHn + k;                        \
            areg = *(const uint4*)p;                                              \
        } else areg = make_uint4(0u, 0u, 0u, 0u);                                 \
        breg = *(const uint4*)(Wte + (size_t)(n0 + arow) * KD + (K0) + achk);     \
    }
    #define ESTORE(BUF)                                                           \
    { *(uint4*)&As[BUF][arow][achk] = areg;                                       \
      *(uint4*)&Bs[BUF][arow][achk] = breg; }
    #define ECOMP(BUF)                                                            \
    {                                                                             \
        unsigned a[4][4], b[4][2];                                                \
        MMA_FRAG_A(a, As, BUF)                                                    \
        MMA_FRAG_B(b, Bs, BUF)                                                    \
        MMA_ALL(a, b)                                                             \
    }

    ELOAD(0)
    ESTORE(0)
    __syncthreads();
    int buf = 0;
    for (int kt = 0; kt < NK; kt++) {
        if (kt + 1 < NK) ELOAD((kt + 1) * 16)
        ECOMP(buf)
        if (kt + 1 < NK) ESTORE(buf ^ 1)
        __syncthreads();
        buf ^= 1;
    }
    #undef ELOAD
    #undef ESTORE
    #undef ECOMP

    // epilogue
    #pragma unroll
    for (int ni = 0; ni < 4; ni++) {
        const int c = n0 + wn + ni * 8 + 2 * tig;
        const float2 bb = *(const float2*)(bias + (size_t)e * DST + c);
        #pragma unroll
        for (int mi = 0; mi < 4; mi++) {
            const int r0 = wm + mi * 16 + gid;
            const int s0 = srow[r0], s1 = srow[r0 + 8];
            if (G1) {
                if (s0 >= 0) {
                    __half2 o = __floats2half2_rn(gelu_f(acc[mi][ni][0] + bb.x),
                                                  gelu_f(acc[mi][ni][1] + bb.y));
                    *(__half2*)(g_hh_h + (size_t)s0 * DEHn + c) = o;
                }
                if (s1 >= 0) {
                    __half2 o = __floats2half2_rn(gelu_f(acc[mi][ni][2] + bb.x),
                                                  gelu_f(acc[mi][ni][3] + bb.y));
                    *(__half2*)(g_hh_h + (size_t)s1 * DEHn + c) = o;
                }
            } else {
                if (s0 >= 0) {
                    float2 o = make_float2(acc[mi][ni][0] + bb.x, acc[mi][ni][1] + bb.y);
                    *(float2*)(g_eo + (size_t)s0 * Dn + c) = o;
                }
                if (s1 >= 0) {
                    float2 o = make_float2(acc[mi][ni][2] + bb.x, acc[mi][ni][3] + bb.y);
                    *(float2*)(g_eo + (size_t)s1 * Dn + c) = o;
                }
            }
        }
    }
}

// ---------------- K6: weighted combine + residual ----------------
__global__ __launch_bounds__(256) void k_combine(
    const float* __restrict__ h, float* __restrict__ out)
{
    const int t = blockIdx.x;
    const int i = threadIdx.x;
    const float w0 = g_tokw[t * 2 + 0];
    const float w1 = g_tokw[t * 2 + 1];
    const float4 hv = ((const float4*)(h + (size_t)t * Dn))[i];
    const float4 a  = ((const float4*)(g_eo + (size_t)(t * 2 + 0) * Dn))[i];
    const float4 b  = ((const float4*)(g_eo + (size_t)(t * 2 + 1) * Dn))[i];
    float4 o;
    o.x = hv.x + w0 * a.x + w1 * b.x;
    o.y = hv.y + w0 * a.y + w1 * b.y;
    o.z = hv.z + w0 * a.z + w1 * b.z;
    o.w = hv.w + w0 * a.w + w1 * b.w;
    ((float4*)(out + (size_t)t * Dn))[i] = o;
}

// ---------------- launch ----------------
extern "C" void kernel_launch(void* const* d_in, const int* in_sizes, int n_in,
                              void* d_out, int out_size)
{
    const float* h         = (const float*)d_in[0];
    const float* feat      = (const float*)d_in[1];
    const float* ln_g      = (const float*)d_in[2];
    const float* ln_b      = (const float*)d_in[3];
    const float* Wsf       = (const float*)d_in[4];
    const float* bsf       = (const float*)d_in[5];
    const float* Wr1       = (const float*)d_in[6];
    const float* br1       = (const float*)d_in[7];
    const float* Wr2       = (const float*)d_in[8];
    const float* br2       = (const float*)d_in[9];
    const float* Wef       = (const float*)d_in[10];
    const float* bef       = (const float*)d_in[11];
    const float* We1       = (const float*)d_in[12];
    const float* be1       = (const float*)d_in[13];
    const float* We2       = (const float*)d_in[14];
    const float* be2       = (const float*)d_in[15];
    const int*   stage_idx = (const int*)d_in[16];
    const int*   expert_idx= (const int*)d_in[17];
    float* out = (float*)d_out;

    __half* We1t; cudaGetSymbolAddress((void**)&We1t, g_We1t_h);
    __half* We2t; cudaGetSymbolAddress((void**)&We2t, g_We2t_h);
    __half* Wr1th; cudaGetSymbolAddress((void**)&Wr1th, g_Wr1t_h);
    __half* Wr1tl; cudaGetSymbolAddress((void**)&Wr1tl, g_Wr1t_l);

    // 1: ln (+ zero cnt, + hi/lo split)
    k_ln<<<Tn, 256>>>(h, feat, ln_g, ln_b, Wsf, bsf, stage_idx);
    // 2: We1 transpose
    k_transpose_h<<<dim3(DEHn / 32, KINn / 32, En), dim3(32, 8)>>>(We1, We1t, KINn, DEHn);
    // 3: Wr1 transpose hi/lo
    k_transpose_hl<<<dim3(DRHn / 32, KINn / 32, 1), dim3(32, 8)>>>(Wr1, Wr1th, Wr1tl, KINn, DRHn);
    // 4: router gemm (split fp16 -> fp32-class)
    k_router_gemm_split<<<dim3(DRHn / 128, Tn / 128), 256>>>(br1);
    // 5: topk + fused eemb
    k_router_topk<<<Tn / 8, 256>>>(Wr2, br2, feat, Wef, bef, expert_idx);
    // 6: expert GEMM1  <-- profiled launch
    k_exp_gemm_h<true><<<dim3(Tn / 128, DEHn / 128, En), 256>>>(We1t, be1);
    // 7: We2 transpose
    k_transpose_h<<<dim3(Dn / 32, DEHn / 32, En), dim3(32, 8)>>>(We2, We2t, DEHn, Dn);
    // 8: expert GEMM2
    k_exp_gemm_h<false><<<dim3(Tn / 128, Dn / 128, En), 256>>>(We2t, be2);
    // 9: combine
    k_combine<<<Tn, 256>>>(h, out);
}